// round 13
// baseline (speedup 1.0000x reference)
#include <cuda_runtime.h>
#include <cuda_fp16.h>
#include <cstdint>

// Problem constants
#define D 512
#define S 32
#define H 64
#define MROWS 256           // rows per CTA
#define THREADS 256         // 8 warps, warp = 32 rows x 64 n (MMA phase)
#define BSTRIDE 144         // bytes per B n-row (64 fp16 k + pad)
#define BTILE (64*BSTRIDE)  // 9216 B (fp16 W tile)
#define SLOT_BYTES (MROWS*64)   // 16 KB: 256 rows x 32 fp16

// smem byte offsets
#define SM_A    0                          // 4 group slots (ring)
#define SM_B0   (SM_A + 4*SLOT_BYTES)      // 65536 (+buf*BTILE, 4 buffers)
#define SM_SKP  (SM_B0 + 4*BTILE)          // 102400 (256 floats)
#define SM_TOTAL (SM_SKP + MROWS*4)        // 103424 -> 2 CTAs/SM

// W1 pre-rounded fp16, n-major: [s][n=64][k=72pad]
__device__ __half  g_Bh[S * 64 * 72];
__device__ float2  g_b1w2[S * H];
__device__ float   g_extras;        // skip_b + sum(b2)

// ------------------------------------------------------------------ helpers
__device__ __forceinline__ unsigned smem_u32(const void* p) {
    return (unsigned)__cvta_generic_to_shared(p);
}
__device__ __forceinline__ unsigned pack_h2(float a, float b) {
    __half2 h = __floats2half2_rn(a, b);
    return *reinterpret_cast<unsigned*>(&h);
}

#define LDSM_X4(r0,r1,r2,r3,addr) \
    asm volatile("ldmatrix.sync.aligned.m8n8.x4.shared.b16 {%0,%1,%2,%3}, [%4];" \
        : "=r"(r0),"=r"(r1),"=r"(r2),"=r"(r3) : "r"(addr))

#define MMA_F16(d,a0,a1,a2,a3,b0,b1) \
    asm volatile("mma.sync.aligned.m16n8k16.row.col.f32.f16.f16.f32 " \
        "{%0,%1,%2,%3}, {%4,%5,%6,%7}, {%8,%9}, {%0,%1,%2,%3};" \
        : "+f"((d)[0]),"+f"((d)[1]),"+f"((d)[2]),"+f"((d)[3]) \
        : "r"(a0),"r"(a1),"r"(a2),"r"(a3),"r"(b0),"r"(b1))

#define CP16(dst, src) \
    asm volatile("cp.async.cg.shared.global [%0], [%1], 16;" :: "r"(dst), "l"(src))
#define CP_COMMIT() asm volatile("cp.async.commit_group;")
#define CP_WAIT0()  asm volatile("cp.async.wait_group 0;")

// ------------------------------------------------------------------ fused prep
__global__ void prep_all(const float* __restrict__ W1,
                         const float* __restrict__ skip_b,
                         const float* __restrict__ b1,
                         const float* __restrict__ W2,
                         const float* __restrict__ b2)
{
    int idx = blockIdx.x * blockDim.x + threadIdx.x;
    if (idx < S * 64 * 72) {
        int s = idx / (64 * 72);
        int rem = idx % (64 * 72);
        int n = rem / 72;
        int k = rem % 72;
        float v = (k < 64) ? W1[(size_t)s * 4096 + (size_t)k * 64 + n] : 0.f;
        g_Bh[idx] = __float2half_rn(v);
        return;
    }
    int r = idx - S * 64 * 72;
    if (r < S * H) { g_b1w2[r] = make_float2(b1[r], W2[r]); return; }
    r -= S * H;
    if (r == 0) {
        float e = skip_b[0];
        for (int s = 0; s < S; ++s) e += b2[s];
        g_extras = e;
    }
}

// ------------------------------------------------------------------ main
// Position p=0..31: seg = (p&1)*16 + (p>>1); groups ga=p>>1, gb=(ga+1+(p&1))&15.
// Slot of group g = g&3. Prologue: full groups 0,1,2 + B(seg 0,16).
// Pair pp handles positions (2pp, 2pp+1); loads halves 0/1 of group (pp+3)&15;
// stages B for pair pp+1 into buffers ((pp+1)&1)*2 + {0,1}.
// ONE __syncthreads per PAIR (write->read separation re-verified).
__global__ void __launch_bounds__(THREADS, 2)
hybrid_main(const float* __restrict__ x,
            const float* __restrict__ skip_w,
            float* __restrict__ out)
{
    extern __shared__ char smem[];
    const unsigned sbase = smem_u32(smem);
    const int tid  = threadIdx.x;
    const int lane = tid & 31;
    const int wid  = tid >> 5;
    const int rowbase = blockIdx.x * MROWS;

    // A ldmatrix lane offsets within a slot (XOR-swizzled 16B chunks)
    const int row_l = (lane & 7) + ((lane >> 3) & 1) * 8;
    const int swz   = (row_l >> 1) & 3;
    const unsigned aoff0 = row_l * 64 + (((0 + (lane >> 4)) ^ swz) * 16);
    const unsigned aoff1 = row_l * 64 + (((2 + (lane >> 4)) ^ swz) * 16);
    const unsigned awarp = wid * 2048;

    // B ldmatrix (non-trans x4, n-major rows)
    const int bg = lane >> 3;
    const unsigned b_base = sbase + SM_B0
        + (((bg >> 1) * 8) + (lane & 7)) * BSTRIDE + (bg & 1) * 16;

    // gather identity: 8 lanes cover one full 128B line per row
    const int g_r = wid * 4 + (lane >> 3);
    const int g_c = lane & 7;
    const unsigned csw = (((g_c >> 1) ^ ((g_r >> 1) & 3)) * 16) + (g_c & 1) * 8;

    float skacc[8] = {0.f,0.f,0.f,0.f,0.f,0.f,0.f,0.f};
    float rowacc[2][2] = {{0.f, 0.f}, {0.f, 0.f}};

    auto stage_B = [&](int seg, int buf) {
        const char* gbp = reinterpret_cast<const char*>(g_Bh) + (size_t)seg * BTILE;
        const unsigned db = sbase + SM_B0 + buf * BTILE;
        #pragma unroll
        for (int i = 0; i < 3; ++i) {
            int j = tid + i * THREADS;
            if (j < BTILE / 16) CP16(db + j * 16, gbp + j * 16);
        }
    };

    // ---------------- prologue: B(seg 0,16) + full groups 0,1,2 ----------------
    stage_B(0, 0);
    stage_B(16, 1);
    CP_COMMIT();
    #pragma unroll
    for (int g = 0; g < 3; ++g) {
        char* slot = smem + SM_A + g * SLOT_BYTES;
        const float* xg = x + (size_t)rowbase * D + g * 32 + g_c * 4;
        float4 w = *reinterpret_cast<const float4*>(skip_w + g * 32 + g_c * 4);
        #pragma unroll
        for (int it = 0; it < 8; ++it) {
            const int r = it * 32 + g_r;
            float4 v = *reinterpret_cast<const float4*>(xg + (size_t)r * D);
            skacc[it] += v.x*w.x + v.y*w.y + v.z*w.z + v.w*w.w;
            uint2 hv = make_uint2(pack_h2(v.x, v.y), pack_h2(v.z, v.w));
            *reinterpret_cast<uint2*>(slot + r * 64 + csw) = hv;
        }
    }

    for (int pp = 0; pp < 16; ++pp) {
        const int gl = (pp + 3) & 15;
        const bool do_load = (pp < 15);
        const bool do_skip = (pp <= 12);
        char* lslot = smem + SM_A + (gl & 3) * SLOT_BYTES;
        const float* lxg = x + (size_t)rowbase * D + gl * 32 + g_c * 4;
        float4 lw = make_float4(0.f,0.f,0.f,0.f);
        if (do_skip) lw = *reinterpret_cast<const float4*>(skip_w + gl * 32 + g_c * 4);

        const int buf_even = (pp & 1) * 2;

        CP_WAIT0();          // both B tiles for this pair landed
        __syncthreads();     // the ONLY barrier for this pair

        // stage B for next pair (both segments, one commit group)
        if (pp < 15) {
            const int nb = ((pp + 1) & 1) * 2;
            stage_B(pp + 1,      nb);
            stage_B(16 + pp + 1, nb + 1);
            CP_COMMIT();
        }

        // =========================== even phase: p=2pp ===========================
        {
            if (do_load) {                             // half 0 of group gl
                #pragma unroll
                for (int i = 0; i < 4; ++i) {
                    const int r = i * 32 + g_r;
                    float4 v = *reinterpret_cast<const float4*>(lxg + (size_t)r * D);
                    if (do_skip) skacc[i] += v.x*lw.x + v.y*lw.y + v.z*lw.z + v.w*lw.w;
                    uint2 hv = make_uint2(pack_h2(v.x, v.y), pack_h2(v.z, v.w));
                    *reinterpret_cast<uint2*>(lslot + r * 64 + csw) = hv;
                }
            }
            float d[2][8][4];
            #pragma unroll
            for (int mt = 0; mt < 2; ++mt)
                #pragma unroll
                for (int nt = 0; nt < 8; ++nt)
                    { d[mt][nt][0]=0.f; d[mt][nt][1]=0.f; d[mt][nt][2]=0.f; d[mt][nt][3]=0.f; }
            const unsigned slota = sbase + SM_A + (pp & 3) * SLOT_BYTES + awarp;
            const unsigned slotb = sbase + SM_A + ((pp + 1) & 3) * SLOT_BYTES + awarp;
            const unsigned bseg = b_base + buf_even * BTILE;
            #pragma unroll
            for (int kk = 0; kk < 4; ++kk) {
                const unsigned abase = ((kk < 2) ? slota : slotb) + ((kk & 1) ? aoff1 : aoff0);
                unsigned ah[2][4];
                #pragma unroll
                for (int mt = 0; mt < 2; ++mt)
                    LDSM_X4(ah[mt][0], ah[mt][1], ah[mt][2], ah[mt][3], abase + mt * 1024);
                #pragma unroll
                for (int ntp = 0; ntp < 4; ++ntp) {
                    unsigned bh0, bh1, bh2, bh3;
                    LDSM_X4(bh0, bh1, bh2, bh3, bseg + ntp * 2304 + kk * 32);
                    #pragma unroll
                    for (int mt = 0; mt < 2; ++mt) {
                        MMA_F16(d[mt][2*ntp],   ah[mt][0],ah[mt][1],ah[mt][2],ah[mt][3], bh0, bh1);
                        MMA_F16(d[mt][2*ntp+1], ah[mt][0],ah[mt][1],ah[mt][2],ah[mt][3], bh2, bh3);
                    }
                }
            }
            const float2* bw = g_b1w2 + pp * H;
            const int cbase = 2 * (lane & 3);
            #pragma unroll
            for (int mt = 0; mt < 2; ++mt) {
                float p0 = 0.f, p1 = 0.f;
                #pragma unroll
                for (int nt = 0; nt < 8; ++nt) {
                    const float2 bw0 = bw[nt * 8 + cbase];
                    const float2 bw1 = bw[nt * 8 + cbase + 1];
                    p0 += fmaxf(d[mt][nt][0] + bw0.x, 0.f) * bw0.y;
                    p0 += fmaxf(d[mt][nt][1] + bw1.x, 0.f) * bw1.y;
                    p1 += fmaxf(d[mt][nt][2] + bw0.x, 0.f) * bw0.y;
                    p1 += fmaxf(d[mt][nt][3] + bw1.x, 0.f) * bw1.y;
                }
                p0 += __shfl_xor_sync(0xffffffffu, p0, 1);
                p0 += __shfl_xor_sync(0xffffffffu, p0, 2);
                p1 += __shfl_xor_sync(0xffffffffu, p1, 1);
                p1 += __shfl_xor_sync(0xffffffffu, p1, 2);
                rowacc[mt][0] += p0;
                rowacc[mt][1] += p1;
            }
        }

        // =========================== odd phase: p=2pp+1 ==========================
        {
            if (do_load) {                             // half 1 of group gl
                #pragma unroll
                for (int i = 0; i < 4; ++i) {
                    const int r = (4 + i) * 32 + g_r;
                    float4 v = *reinterpret_cast<const float4*>(lxg + (size_t)r * D);
                    if (do_skip) skacc[4 + i] += v.x*lw.x + v.y*lw.y + v.z*lw.z + v.w*lw.w;
                    uint2 hv = make_uint2(pack_h2(v.x, v.y), pack_h2(v.z, v.w));
                    *reinterpret_cast<uint2*>(lslot + r * 64 + csw) = hv;
                }
            }
            float d[2][8][4];
            #pragma unroll
            for (int mt = 0; mt < 2; ++mt)
                #pragma unroll
                for (int nt = 0; nt < 8; ++nt)
                    { d[mt][nt][0]=0.f; d[mt][nt][1]=0.f; d[mt][nt][2]=0.f; d[mt][nt][3]=0.f; }
            const unsigned slota = sbase + SM_A + (pp & 3) * SLOT_BYTES + awarp;
            const unsigned slotb = sbase + SM_A + ((pp + 2) & 3) * SLOT_BYTES + awarp;
            const unsigned bseg = b_base + (buf_even + 1) * BTILE;
            #pragma unroll
            for (int kk = 0; kk < 4; ++kk) {
                const unsigned abase = ((kk < 2) ? slota : slotb) + ((kk & 1) ? aoff1 : aoff0);
                unsigned ah[2][4];
                #pragma unroll
                for (int mt = 0; mt < 2; ++mt)
                    LDSM_X4(ah[mt][0], ah[mt][1], ah[mt][2], ah[mt][3], abase + mt * 1024);
                #pragma unroll
                for (int ntp = 0; ntp < 4; ++ntp) {
                    unsigned bh0, bh1, bh2, bh3;
                    LDSM_X4(bh0, bh1, bh2, bh3, bseg + ntp * 2304 + kk * 32);
                    #pragma unroll
                    for (int mt = 0; mt < 2; ++mt) {
                        MMA_F16(d[mt][2*ntp],   ah[mt][0],ah[mt][1],ah[mt][2],ah[mt][3], bh0, bh1);
                        MMA_F16(d[mt][2*ntp+1], ah[mt][0],ah[mt][1],ah[mt][2],ah[mt][3], bh2, bh3);
                    }
                }
            }
            const float2* bw = g_b1w2 + (16 + pp) * H;
            const int cbase = 2 * (lane & 3);
            #pragma unroll
            for (int mt = 0; mt < 2; ++mt) {
                float p0 = 0.f, p1 = 0.f;
                #pragma unroll
                for (int nt = 0; nt < 8; ++nt) {
                    const float2 bw0 = bw[nt * 8 + cbase];
                    const float2 bw1 = bw[nt * 8 + cbase + 1];
                    p0 += fmaxf(d[mt][nt][0] + bw0.x, 0.f) * bw0.y;
                    p0 += fmaxf(d[mt][nt][1] + bw1.x, 0.f) * bw1.y;
                    p1 += fmaxf(d[mt][nt][2] + bw0.x, 0.f) * bw0.y;
                    p1 += fmaxf(d[mt][nt][3] + bw1.x, 0.f) * bw1.y;
                }
                p0 += __shfl_xor_sync(0xffffffffu, p0, 1);
                p0 += __shfl_xor_sync(0xffffffffu, p0, 2);
                p1 += __shfl_xor_sync(0xffffffffu, p1, 1);
                p1 += __shfl_xor_sync(0xffffffffu, p1, 2);
                rowacc[mt][0] += p0;
                rowacc[mt][1] += p1;
            }
        }
    }

    // ---- finalize: reduce skip partials over the 8 lanes sharing each row
    {
        float* skp = reinterpret_cast<float*>(smem + SM_SKP);
        #pragma unroll
        for (int it = 0; it < 8; ++it) {
            float v = skacc[it];
            v += __shfl_xor_sync(0xffffffffu, v, 1);
            v += __shfl_xor_sync(0xffffffffu, v, 2);
            v += __shfl_xor_sync(0xffffffffu, v, 4);
            if (g_c == 0) skp[it * 32 + g_r] = v;
        }
    }
    __syncthreads();

    if ((lane & 3) == 0) {
        const float* skp = reinterpret_cast<const float*>(smem + SM_SKP);
        const float extras = g_extras;
        #pragma unroll
        for (int mt = 0; mt < 2; ++mt) {
            const int lr = wid * 32 + mt * 16 + (lane >> 2);
            float v0 = rowacc[mt][0] + extras + skp[lr];
            float v1 = rowacc[mt][1] + extras + skp[lr + 8];
            out[rowbase + lr]     = fminf(fmaxf(v0, -20.0f), 20.0f);
            out[rowbase + lr + 8] = fminf(fmaxf(v1, -20.0f), 20.0f);
        }
    }
}

// ------------------------------------------------------------------ launch
extern "C" void kernel_launch(void* const* d_in, const int* in_sizes, int n_in,
                              void* d_out, int out_size)
{
    const float* x       = (const float*)d_in[0];
    const float* skip_w  = (const float*)d_in[1];
    const float* skip_b  = (const float*)d_in[2];
    const float* W1      = (const float*)d_in[3];
    const float* b1      = (const float*)d_in[4];
    const float* W2      = (const float*)d_in[5];
    const float* b2      = (const float*)d_in[6];
    float* out = (float*)d_out;

    static bool attr_set = false;
    if (!attr_set) {
        cudaFuncSetAttribute(hybrid_main,
                             cudaFuncAttributeMaxDynamicSharedMemorySize, SM_TOTAL);
        attr_set = true;
    }

    const int prep_items = S * 64 * 72 + S * H + 1;
    prep_all<<<(prep_items + 255) / 256, 256>>>(W1, skip_b, b1, W2, b2);

    const int nrows = in_sizes[0] / D;   // 65536
    const int grid  = nrows / MROWS;     // 256
    hybrid_main<<<grid, THREADS, SM_TOTAL>>>(x, skip_w, out);
}

// round 14
// speedup vs baseline: 1.0605x; 1.0605x over previous
#include <cuda_runtime.h>
#include <cuda_fp16.h>
#include <cstdint>

// Problem constants
#define D 512
#define S 32
#define H 64
#define MROWS 256           // rows per CTA
#define THREADS 256         // 8 warps, warp = 32 rows x 64 n (MMA phase)
#define BSTRIDE 144         // bytes per B n-row (64 fp16 k + pad)
#define BTILE (64*BSTRIDE)  // 9216 B (fp16 W tile)
#define SLOT_BYTES (MROWS*64)   // 16 KB: 256 rows x 32 fp16

// smem byte offsets
#define SM_A    0                          // 4 group slots (ring)
#define SM_B0   (SM_A + 4*SLOT_BYTES)      // 65536 (+buf*BTILE)
#define SM_SKP  (SM_B0 + 2*BTILE)          // 83968 (256 floats)
#define SM_TOTAL (SM_SKP + MROWS*4)        // 84992 -> 2 CTAs/SM

// W1 pre-rounded fp16, n-major: [s][n=64][k=72pad]
__device__ __half  g_Bh[S * 64 * 72];
__device__ float2  g_b1w2[S * H];
__device__ float   g_extras;        // skip_b + sum(b2)

// ------------------------------------------------------------------ helpers
__device__ __forceinline__ unsigned smem_u32(const void* p) {
    return (unsigned)__cvta_generic_to_shared(p);
}
__device__ __forceinline__ unsigned pack_h2(float a, float b) {
    __half2 h = __floats2half2_rn(a, b);
    return *reinterpret_cast<unsigned*>(&h);
}

#define LDSM_X4(r0,r1,r2,r3,addr) \
    asm volatile("ldmatrix.sync.aligned.m8n8.x4.shared.b16 {%0,%1,%2,%3}, [%4];" \
        : "=r"(r0),"=r"(r1),"=r"(r2),"=r"(r3) : "r"(addr))

#define MMA_F16(d,a0,a1,a2,a3,b0,b1) \
    asm volatile("mma.sync.aligned.m16n8k16.row.col.f32.f16.f16.f32 " \
        "{%0,%1,%2,%3}, {%4,%5,%6,%7}, {%8,%9}, {%0,%1,%2,%3};" \
        : "+f"((d)[0]),"+f"((d)[1]),"+f"((d)[2]),"+f"((d)[3]) \
        : "r"(a0),"r"(a1),"r"(a2),"r"(a3),"r"(b0),"r"(b1))

// first k-step: C = 0 (no accumulator init MOVs needed)
#define MMA_F16_ZC(d,a0,a1,a2,a3,b0,b1) \
    asm volatile("mma.sync.aligned.m16n8k16.row.col.f32.f16.f16.f32 " \
        "{%0,%1,%2,%3}, {%4,%5,%6,%7}, {%8,%9}, {%10,%10,%10,%10};" \
        : "=f"((d)[0]),"=f"((d)[1]),"=f"((d)[2]),"=f"((d)[3]) \
        : "r"(a0),"r"(a1),"r"(a2),"r"(a3),"r"(b0),"r"(b1),"f"(0.f))

#define CP16(dst, src) \
    asm volatile("cp.async.cg.shared.global [%0], [%1], 16;" :: "r"(dst), "l"(src))
#define CP_COMMIT() asm volatile("cp.async.commit_group;")
#define CP_WAIT0()  asm volatile("cp.async.wait_group 0;")

// ------------------------------------------------------------------ fused prep
__global__ void prep_all(const float* __restrict__ W1,
                         const float* __restrict__ skip_b,
                         const float* __restrict__ b1,
                         const float* __restrict__ W2,
                         const float* __restrict__ b2)
{
    int idx = blockIdx.x * blockDim.x + threadIdx.x;
    if (idx < S * 64 * 72) {
        int s = idx / (64 * 72);
        int rem = idx % (64 * 72);
        int n = rem / 72;
        int k = rem % 72;
        float v = (k < 64) ? W1[(size_t)s * 4096 + (size_t)k * 64 + n] : 0.f;
        g_Bh[idx] = __float2half_rn(v);
        return;
    }
    int r = idx - S * 64 * 72;
    if (r < S * H) { g_b1w2[r] = make_float2(b1[r], W2[r]); return; }
    r -= S * H;
    if (r == 0) {
        float e = skip_b[0];
        for (int s = 0; s < S; ++s) e += b2[s];
        g_extras = e;
    }
}

// ------------------------------------------------------------------ main
// Position p=0..31: seg = (p&1)*16 + (p>>1); groups ga=p>>1, gb=(ga+1+(p&1))&15.
// Slot of group g = g&3. Prologue: full groups 0,1,2. Position pair (2pp,2pp+1)
// loads halves 0,1 of group (pp+3)&15 (skip-dot iff pp<=12; nothing at pp=15).
// ONE __syncthreads per position (R12 structure — best measured).
__global__ void __launch_bounds__(THREADS, 2)
hybrid_main(const float* __restrict__ x,
            const float* __restrict__ skip_w,
            float* __restrict__ out)
{
    extern __shared__ char smem[];
    const unsigned sbase = smem_u32(smem);
    const int tid  = threadIdx.x;
    const int lane = tid & 31;
    const int wid  = tid >> 5;
    const int rowbase = blockIdx.x * MROWS;

    // A ldmatrix lane offsets within a slot (XOR-swizzled 16B chunks)
    const int row_l = (lane & 7) + ((lane >> 3) & 1) * 8;
    const int swz   = (row_l >> 1) & 3;
    const unsigned aoff0 = row_l * 64 + (((0 + (lane >> 4)) ^ swz) * 16);
    const unsigned aoff1 = row_l * 64 + (((2 + (lane >> 4)) ^ swz) * 16);
    const unsigned awarp = wid * 2048;

    // B ldmatrix (non-trans x4, n-major rows)
    const int bg = lane >> 3;
    const unsigned b_base = sbase + SM_B0
        + (((bg >> 1) * 8) + (lane & 7)) * BSTRIDE + (bg & 1) * 16;

    // gather identity: 8 lanes cover one full 128B line per row
    const int g_r = wid * 4 + (lane >> 3);
    const int g_c = lane & 7;
    const unsigned csw = (((g_c >> 1) ^ ((g_r >> 1) & 3)) * 16) + (g_c & 1) * 8;

    float skacc[8] = {0.f,0.f,0.f,0.f,0.f,0.f,0.f,0.f};
    float rowacc[2][2] = {{0.f, 0.f}, {0.f, 0.f}};

    auto stage_B = [&](int seg, int buf) {
        const char* gbp = reinterpret_cast<const char*>(g_Bh) + (size_t)seg * BTILE;
        const unsigned db = sbase + SM_B0 + buf * BTILE;
        #pragma unroll
        for (int i = 0; i < 3; ++i) {
            int j = tid + i * THREADS;
            if (j < BTILE / 16) CP16(db + j * 16, gbp + j * 16);
        }
        CP_COMMIT();
    };

    // MMA + epilogue for one position (seg, slots, B buffer)
    auto do_mma = [&](int seg, unsigned slota, unsigned slotb, unsigned bseg) {
        float d[2][8][4];
        #pragma unroll
        for (int kk = 0; kk < 4; ++kk) {
            const unsigned abase = ((kk < 2) ? slota : slotb) + ((kk & 1) ? aoff1 : aoff0);
            unsigned ah[2][4];
            #pragma unroll
            for (int mt = 0; mt < 2; ++mt)
                LDSM_X4(ah[mt][0], ah[mt][1], ah[mt][2], ah[mt][3], abase + mt * 1024);
            // B-fragment double buffer: keep one LDSM in flight
            unsigned bh[2][4];
            LDSM_X4(bh[0][0], bh[0][1], bh[0][2], bh[0][3], bseg + kk * 32);
            #pragma unroll
            for (int ntp = 0; ntp < 4; ++ntp) {
                const int cur = ntp & 1;
                if (ntp < 3)
                    LDSM_X4(bh[cur^1][0], bh[cur^1][1], bh[cur^1][2], bh[cur^1][3],
                            bseg + (ntp + 1) * 2304 + kk * 32);
                #pragma unroll
                for (int mt = 0; mt < 2; ++mt) {
                    if (kk == 0) {
                        MMA_F16_ZC(d[mt][2*ntp],   ah[mt][0],ah[mt][1],ah[mt][2],ah[mt][3], bh[cur][0], bh[cur][1]);
                        MMA_F16_ZC(d[mt][2*ntp+1], ah[mt][0],ah[mt][1],ah[mt][2],ah[mt][3], bh[cur][2], bh[cur][3]);
                    } else {
                        MMA_F16(d[mt][2*ntp],   ah[mt][0],ah[mt][1],ah[mt][2],ah[mt][3], bh[cur][0], bh[cur][1]);
                        MMA_F16(d[mt][2*ntp+1], ah[mt][0],ah[mt][1],ah[mt][2],ah[mt][3], bh[cur][2], bh[cur][3]);
                    }
                }
            }
        }
        const float2* bw = g_b1w2 + seg * H;
        const int cbase = 2 * (lane & 3);
        #pragma unroll
        for (int mt = 0; mt < 2; ++mt) {
            float p0 = 0.f, p1 = 0.f;
            #pragma unroll
            for (int nt = 0; nt < 8; ++nt) {
                const float2 bw0 = bw[nt * 8 + cbase];
                const float2 bw1 = bw[nt * 8 + cbase + 1];
                p0 += fmaxf(d[mt][nt][0] + bw0.x, 0.f) * bw0.y;
                p0 += fmaxf(d[mt][nt][1] + bw1.x, 0.f) * bw1.y;
                p1 += fmaxf(d[mt][nt][2] + bw0.x, 0.f) * bw0.y;
                p1 += fmaxf(d[mt][nt][3] + bw1.x, 0.f) * bw1.y;
            }
            p0 += __shfl_xor_sync(0xffffffffu, p0, 1);
            p0 += __shfl_xor_sync(0xffffffffu, p0, 2);
            p1 += __shfl_xor_sync(0xffffffffu, p1, 1);
            p1 += __shfl_xor_sync(0xffffffffu, p1, 2);
            rowacc[mt][0] += p0;
            rowacc[mt][1] += p1;
        }
    };

    // ---------------- prologue: B(seg 0) + full groups 0,1,2 ----------------
    stage_B(0, 0);
    #pragma unroll
    for (int g = 0; g < 3; ++g) {
        char* slot = smem + SM_A + g * SLOT_BYTES;
        const float* xg = x + (size_t)rowbase * D + g * 32 + g_c * 4;
        float4 w = *reinterpret_cast<const float4*>(skip_w + g * 32 + g_c * 4);
        #pragma unroll
        for (int it = 0; it < 8; ++it) {
            const int r = it * 32 + g_r;
            float4 v = *reinterpret_cast<const float4*>(xg + (size_t)r * D);
            skacc[it] += v.x*w.x + v.y*w.y + v.z*w.z + v.w*w.w;
            uint2 hv = make_uint2(pack_h2(v.x, v.y), pack_h2(v.z, v.w));
            *reinterpret_cast<uint2*>(slot + r * 64 + csw) = hv;
        }
    }

    for (int pp = 0; pp < 16; ++pp) {
        const int gl = (pp + 3) & 15;
        const bool do_load = (pp < 15);
        const bool do_skip = (pp <= 12);
        char* lslot = smem + SM_A + (gl & 3) * SLOT_BYTES;
        const float* lxg = x + (size_t)rowbase * D + gl * 32 + g_c * 4;
        float4 lw = make_float4(0.f,0.f,0.f,0.f);
        if (do_skip) lw = *reinterpret_cast<const float4*>(skip_w + gl * 32 + g_c * 4);

        // =========================== even phase: p=2pp ===========================
        {
            CP_WAIT0();
            __syncthreads();
            stage_B(16 + pp, 1);                       // B for odd phase
            if (do_load) {                             // half 0 of group gl
                #pragma unroll
                for (int i = 0; i < 4; ++i) {
                    const int r = i * 32 + g_r;
                    float4 v = *reinterpret_cast<const float4*>(lxg + (size_t)r * D);
                    if (do_skip) skacc[i] += v.x*lw.x + v.y*lw.y + v.z*lw.z + v.w*lw.w;
                    uint2 hv = make_uint2(pack_h2(v.x, v.y), pack_h2(v.z, v.w));
                    *reinterpret_cast<uint2*>(lslot + r * 64 + csw) = hv;
                }
            }
            do_mma(pp,
                   sbase + SM_A + (pp & 3) * SLOT_BYTES + awarp,
                   sbase + SM_A + ((pp + 1) & 3) * SLOT_BYTES + awarp,
                   b_base);
        }

        // =========================== odd phase: p=2pp+1 ==========================
        {
            CP_WAIT0();
            __syncthreads();
            if (pp < 15) stage_B(pp + 1, 0);           // B for next even phase
            if (do_load) {                             // half 1 of group gl
                #pragma unroll
                for (int i = 0; i < 4; ++i) {
                    const int r = (4 + i) * 32 + g_r;
                    float4 v = *reinterpret_cast<const float4*>(lxg + (size_t)r * D);
                    if (do_skip) skacc[4 + i] += v.x*lw.x + v.y*lw.y + v.z*lw.z + v.w*lw.w;
                    uint2 hv = make_uint2(pack_h2(v.x, v.y), pack_h2(v.z, v.w));
                    *reinterpret_cast<uint2*>(lslot + r * 64 + csw) = hv;
                }
            }
            do_mma(16 + pp,
                   sbase + SM_A + (pp & 3) * SLOT_BYTES + awarp,
                   sbase + SM_A + ((pp + 2) & 3) * SLOT_BYTES + awarp,
                   b_base + BTILE);
        }
    }

    // ---- finalize: reduce skip partials over the 8 lanes sharing each row
    {
        float* skp = reinterpret_cast<float*>(smem + SM_SKP);
        #pragma unroll
        for (int it = 0; it < 8; ++it) {
            float v = skacc[it];
            v += __shfl_xor_sync(0xffffffffu, v, 1);
            v += __shfl_xor_sync(0xffffffffu, v, 2);
            v += __shfl_xor_sync(0xffffffffu, v, 4);
            if (g_c == 0) skp[it * 32 + g_r] = v;
        }
    }
    __syncthreads();

    if ((lane & 3) == 0) {
        const float* skp = reinterpret_cast<const float*>(smem + SM_SKP);
        const float extras = g_extras;
        #pragma unroll
        for (int mt = 0; mt < 2; ++mt) {
            const int lr = wid * 32 + mt * 16 + (lane >> 2);
            float v0 = rowacc[mt][0] + extras + skp[lr];
            float v1 = rowacc[mt][1] + extras + skp[lr + 8];
            out[rowbase + lr]     = fminf(fmaxf(v0, -20.0f), 20.0f);
            out[rowbase + lr + 8] = fminf(fmaxf(v1, -20.0f), 20.0f);
        }
    }
}

// ------------------------------------------------------------------ launch
extern "C" void kernel_launch(void* const* d_in, const int* in_sizes, int n_in,
                              void* d_out, int out_size)
{
    const float* x       = (const float*)d_in[0];
    const float* skip_w  = (const float*)d_in[1];
    const float* skip_b  = (const float*)d_in[2];
    const float* W1      = (const float*)d_in[3];
    const float* b1      = (const float*)d_in[4];
    const float* W2      = (const float*)d_in[5];
    const float* b2      = (const float*)d_in[6];
    float* out = (float*)d_out;

    static bool attr_set = false;
    if (!attr_set) {
        cudaFuncSetAttribute(hybrid_main,
                             cudaFuncAttributeMaxDynamicSharedMemorySize, SM_TOTAL);
        attr_set = true;
    }

    const int prep_items = S * 64 * 72 + S * H + 1;
    prep_all<<<(prep_items + 255) / 256, 256>>>(W1, skip_b, b1, W2, b2);

    const int nrows = in_sizes[0] / D;   // 65536
    const int grid  = nrows / MROWS;     // 256
    hybrid_main<<<grid, THREADS, SM_TOTAL>>>(x, skip_w, out);
}